// round 5
// baseline (speedup 1.0000x reference)
#include <cuda_runtime.h>
#include <cuda_bf16.h>

#define HW 200704
#define C 192
#define TP 128
#define NH 6
#define D 32
#define PXS 100   // u32 stride for px-major bf16x2 tiles (96 ch-pairs + 4 pad)
#define WST 200   // u32 stride per k-pair row in weight chunk
#define QS  136   // bf16 stride for ch-major q/k tiles
#define MS  (96 * 192)   // u32 per converted weight matrix

// ---------------- scratch ----------------------------------------------------
__device__ unsigned g_wbf[5 * MS];                    // pre,q,k,v,proj bf16x2 [cp][o]
__device__ unsigned g_v[(size_t)(HW / TP) * TP * 96]; // v tiles, px-major bf16x2
__device__ float    g_G[NH * D * D];
__device__ float    g_qs2[C];
__device__ float    g_ks2[C];
__device__ unsigned g_gmbf[C * 16];                   // gm bf16x2 pairs [ch][e/2]

// ---------------- helpers ----------------------------------------------------
__device__ __forceinline__ unsigned packbf(float a, float b) {
    __nv_bfloat162 p = __floats2bfloat162_rn(a, b);
    return *(unsigned*)&p;
}
__device__ __forceinline__ float2 unpbf(unsigned u) {
    __nv_bfloat162 p = *(__nv_bfloat162*)&u;
    return __bfloat1622float2(p);
}
__device__ __forceinline__ void mma_bf16(float d[4], const unsigned a[4],
                                         unsigned b0, unsigned b1) {
    asm volatile(
        "mma.sync.aligned.m16n8k16.row.col.f32.bf16.bf16.f32 "
        "{%0,%1,%2,%3},{%4,%5,%6,%7},{%8,%9},{%0,%1,%2,%3};\n"
        : "+f"(d[0]), "+f"(d[1]), "+f"(d[2]), "+f"(d[3])
        : "r"(a[0]), "r"(a[1]), "r"(a[2]), "r"(a[3]), "r"(b0), "r"(b1));
}

// bf16 GEMM over a px-major [128px][96 cpair] smem tile (stride PXS u32) with a
// pre-converted weight matrix streamed through w_s in K=32 chunks.
// 512 threads, warp grid 4Mx4N: warp tile 32px x 48out. All threads must call.
__device__ __forceinline__ void gemm_bf(const unsigned* a_s, unsigned* w_s,
                                        const unsigned* __restrict__ wg,
                                        float acc[2][6][4], int tid) {
    const int lane = tid & 31, warp = tid >> 5;
    const int gid = lane >> 2, tg = lane & 3;
    const int mb = (warp & 3) * 32, nb = (warp >> 2) * 48;
    for (int ch = 0; ch < 6; ch++) {
        __syncthreads();
        for (int i = tid; i < 3072; i += 512) {
            int j = i / 192, o = i - j * 192;
            w_s[j * WST + o] = wg[ch * 3072 + i];
        }
        __syncthreads();
#pragma unroll
        for (int kl = 0; kl < 2; kl++) {
            const int k2 = ch * 16 + kl * 8;
            unsigned a[2][4];
#pragma unroll
            for (int mt = 0; mt < 2; mt++) {
                const unsigned* ab = a_s + (mb + mt * 16 + gid) * PXS + k2 + tg;
                a[mt][0] = ab[0];
                a[mt][1] = ab[8 * PXS];
                a[mt][2] = ab[4];
                a[mt][3] = ab[8 * PXS + 4];
            }
#pragma unroll
            for (int nt = 0; nt < 6; nt++) {
                const unsigned* wb = w_s + (kl * 8 + tg) * WST + nb + nt * 8 + gid;
                unsigned b0 = wb[0], b1 = wb[4 * WST];
#pragma unroll
                for (int mt = 0; mt < 2; mt++) mma_bf16(acc[mt][nt], a[mt], b0, b1);
            }
        }
    }
}

// ---------------- prep: convert weights to bf16x2 + zero accumulators --------
__global__ void prep_kernel(const float* __restrict__ pre_w,
                            const float* __restrict__ qkv_w,
                            const float* __restrict__ proj_w) {
    int idx = blockIdx.x * 256 + threadIdx.x;
    if (idx < 5 * MS) {
        int m = idx / MS, r = idx - m * MS;
        int cp = r / 192, o = r - cp * 192;
        const float* W = (m == 0) ? pre_w : (m < 4 ? qkv_w + (m - 1) * C * C : proj_w);
        g_wbf[idx] = packbf(W[o * C + 2 * cp], W[o * C + 2 * cp + 1]);
    }
    if (blockIdx.x == 0) {
        for (int i = threadIdx.x; i < NH * D * D; i += 256) g_G[i] = 0.f;
        if (threadIdx.x < C) {
            g_qs2[threadIdx.x] = 0.f;
            g_ks2[threadIdx.x] = 0.f;
        }
    }
}

// ---------------- k12: LN + pre + qkv + Gram (512 thr) -----------------------
__global__ __launch_bounds__(512, 1) void k12(const float* __restrict__ x,
                                              const float* __restrict__ lng,
                                              const float* __restrict__ lnb,
                                              const float* __restrict__ pre_b) {
    extern __shared__ unsigned sm[];
    unsigned* bufA = sm;                               // 13056 u32: x tile -> q_s
    unsigned* y_s  = sm + 13056;                       // 12800
    unsigned* kbuf = sm + 13056 + 12800;               // 13056: k_s
    unsigned* w_s  = sm + 13056 + 12800 + 13056;       // 3200
    float* gb = (float*)(w_s + 3200);                  // g[192], b[192]
    float* mu = gb + 384;                              // 128
    float* rs = mu + 128;                              // 128
    const int tid = threadIdx.x, lane = tid & 31, warp = tid >> 5;
    const int gid = lane >> 2, tg = lane & 3;
    const int mb = (warp & 3) * 32, nb = (warp >> 2) * 48;
    const int p0 = blockIdx.x * TP;

    for (int i = tid; i < C; i += 512) {
        gb[i]       = lng[i];
        gb[192 + i] = lnb[i];
    }
    // x transpose into px-major bf16x2
    for (int c2 = warp; c2 < 96; c2 += 16) {
        int c = 2 * c2;
#pragma unroll
        for (int pb = 0; pb < 128; pb += 32) {
            float v0 = x[(size_t)c * HW + p0 + pb + lane];
            float v1 = x[(size_t)(c + 1) * HW + p0 + pb + lane];
            bufA[(pb + lane) * PXS + c2] = packbf(v0, v1);
        }
    }
    __syncthreads();
    // LN stats: warp per px row, lanes over channel pairs, shuffle reduce
    for (int px = warp; px < 128; px += 16) {
        float s = 0.f, s2 = 0.f;
        for (int c2 = lane; c2 < 96; c2 += 32) {
            float2 f = unpbf(bufA[px * PXS + c2]);
            s += f.x + f.y;
            s2 += f.x * f.x + f.y * f.y;
        }
#pragma unroll
        for (int o = 16; o; o >>= 1) {
            s  += __shfl_xor_sync(~0u, s, o);
            s2 += __shfl_xor_sync(~0u, s2, o);
        }
        if (lane == 0) {
            float m = s * (1.f / C), v = s2 * (1.f / C) - m * m;
            mu[px] = m;
            rs[px] = rsqrtf(v + 1e-5f);
        }
    }
    __syncthreads();
    // apply LN
    for (int px = warp; px < 128; px += 16) {
        float m = mu[px], r = rs[px];
        for (int c2 = lane; c2 < 96; c2 += 32) {
            float2 f = unpbf(bufA[px * PXS + c2]);
            f.x = (f.x - m) * r * gb[2 * c2]     + gb[192 + 2 * c2];
            f.y = (f.y - m) * r * gb[2 * c2 + 1] + gb[192 + 2 * c2 + 1];
            bufA[px * PXS + c2] = packbf(f.x, f.y);
        }
    }

    float acc[2][6][4];
    // ---- pre GEMM (bias init) ----
#pragma unroll
    for (int nt = 0; nt < 6; nt++) {
        int o = nb + nt * 8 + 2 * tg;
        float b0 = __ldg(&pre_b[o]), b1 = __ldg(&pre_b[o + 1]);
#pragma unroll
        for (int mt = 0; mt < 2; mt++) {
            acc[mt][nt][0] = b0; acc[mt][nt][1] = b1;
            acc[mt][nt][2] = b0; acc[mt][nt][3] = b1;
        }
    }
    gemm_bf(bufA, w_s, g_wbf, acc, tid);
    __syncthreads();   // bufA reads done everywhere before y overwrite pattern reuse
#pragma unroll
    for (int mt = 0; mt < 2; mt++)
#pragma unroll
        for (int nt = 0; nt < 6; nt++) {
            int px = mb + mt * 16 + gid, cp = (nb + nt * 8) / 2 + tg;
            y_s[px * PXS + cp]       = packbf(acc[mt][nt][0], acc[mt][nt][1]);
            y_s[(px + 8) * PXS + cp] = packbf(acc[mt][nt][2], acc[mt][nt][3]);
        }
    // ---- q GEMM -> ch-major q_s (over bufA) ----
#pragma unroll
    for (int mt = 0; mt < 2; mt++)
#pragma unroll
        for (int nt = 0; nt < 6; nt++)
#pragma unroll
            for (int r = 0; r < 4; r++) acc[mt][nt][r] = 0.f;
    gemm_bf(y_s, w_s, g_wbf + MS, acc, tid);
    {
        __nv_bfloat16* q_s = (__nv_bfloat16*)bufA;
#pragma unroll
        for (int mt = 0; mt < 2; mt++)
#pragma unroll
            for (int nt = 0; nt < 6; nt++) {
                int o = nb + nt * 8 + 2 * tg, p = mb + mt * 16 + gid;
                q_s[o * QS + p]           = __float2bfloat16(acc[mt][nt][0]);
                q_s[(o + 1) * QS + p]     = __float2bfloat16(acc[mt][nt][1]);
                q_s[o * QS + p + 8]       = __float2bfloat16(acc[mt][nt][2]);
                q_s[(o + 1) * QS + p + 8] = __float2bfloat16(acc[mt][nt][3]);
            }
    }
    // ---- k GEMM -> ch-major k_s ----
#pragma unroll
    for (int mt = 0; mt < 2; mt++)
#pragma unroll
        for (int nt = 0; nt < 6; nt++)
#pragma unroll
            for (int r = 0; r < 4; r++) acc[mt][nt][r] = 0.f;
    gemm_bf(y_s, w_s, g_wbf + 2 * MS, acc, tid);
    {
        __nv_bfloat16* k_s = (__nv_bfloat16*)kbuf;
#pragma unroll
        for (int mt = 0; mt < 2; mt++)
#pragma unroll
            for (int nt = 0; nt < 6; nt++) {
                int o = nb + nt * 8 + 2 * tg, p = mb + mt * 16 + gid;
                k_s[o * QS + p]           = __float2bfloat16(acc[mt][nt][0]);
                k_s[(o + 1) * QS + p]     = __float2bfloat16(acc[mt][nt][1]);
                k_s[o * QS + p + 8]       = __float2bfloat16(acc[mt][nt][2]);
                k_s[(o + 1) * QS + p + 8] = __float2bfloat16(acc[mt][nt][3]);
            }
    }
    // ---- v GEMM -> DRAM bf16x2 px-major ----
#pragma unroll
    for (int mt = 0; mt < 2; mt++)
#pragma unroll
        for (int nt = 0; nt < 6; nt++)
#pragma unroll
            for (int r = 0; r < 4; r++) acc[mt][nt][r] = 0.f;
    gemm_bf(y_s, w_s, g_wbf + 3 * MS, acc, tid);
    {
        unsigned* vt = g_v + (size_t)blockIdx.x * (TP * 96);
#pragma unroll
        for (int mt = 0; mt < 2; mt++)
#pragma unroll
            for (int nt = 0; nt < 6; nt++) {
                int px = mb + mt * 16 + gid, cp = (nb + nt * 8) / 2 + tg;
                vt[px * 96 + cp]       = packbf(acc[mt][nt][0], acc[mt][nt][1]);
                vt[(px + 8) * 96 + cp] = packbf(acc[mt][nt][2], acc[mt][nt][3]);
            }
    }
    __syncthreads();

    // ---- Gram: 12 warps = 6 heads x 2 px-halves, bf16 mma -------------------
    if (warp < 12) {
        const __nv_bfloat16* q_s = (const __nv_bfloat16*)bufA;
        const __nv_bfloat16* k_s = (const __nv_bfloat16*)kbuf;
        const int h = warp >> 1;
        const int kc0 = (warp & 1) * 64;
        float dG[2][4][4];
#pragma unroll
        for (int mt = 0; mt < 2; mt++)
#pragma unroll
            for (int nt = 0; nt < 4; nt++)
#pragma unroll
                for (int r = 0; r < 4; r++) dG[mt][nt][r] = 0.f;
        for (int kc = kc0; kc < kc0 + 64; kc += 16) {
            unsigned a[2][4];
#pragma unroll
            for (int mt = 0; mt < 2; mt++) {
                const __nv_bfloat16* ab = q_s + (h * 32 + mt * 16 + gid) * QS + kc + 2 * tg;
                a[mt][0] = *(const unsigned*)(ab);
                a[mt][1] = *(const unsigned*)(ab + 8 * QS);
                a[mt][2] = *(const unsigned*)(ab + 8);
                a[mt][3] = *(const unsigned*)(ab + 8 * QS + 8);
            }
#pragma unroll
            for (int nt = 0; nt < 4; nt++) {
                const __nv_bfloat16* bb = k_s + (h * 32 + nt * 8 + gid) * QS + kc + 2 * tg;
                unsigned b0 = *(const unsigned*)(bb);
                unsigned b1 = *(const unsigned*)(bb + 8);
#pragma unroll
                for (int mt = 0; mt < 2; mt++) mma_bf16(dG[mt][nt], a[mt], b0, b1);
            }
        }
#pragma unroll
        for (int mt = 0; mt < 2; mt++)
#pragma unroll
            for (int nt = 0; nt < 4; nt++) {
                int r0 = h * 32 + mt * 16 + gid, c0 = nt * 8 + 2 * tg;
                atomicAdd(&g_G[r0 * 32 + c0],           dG[mt][nt][0]);
                atomicAdd(&g_G[r0 * 32 + c0 + 1],       dG[mt][nt][1]);
                atomicAdd(&g_G[(r0 + 8) * 32 + c0],     dG[mt][nt][2]);
                atomicAdd(&g_G[(r0 + 8) * 32 + c0 + 1], dG[mt][nt][3]);
            }
    }
    // squared norms from the same bf16 values
    for (int i = tid; i < 2 * C; i += 512) {
        const unsigned* arr = (i < C) ? bufA : kbuf;
        int row = (i < C) ? i : i - C;
        const unsigned* rp = arr + row * (QS / 2);
        float s = 0.f;
        for (int p = 0; p < 64; p++) {
            float2 f = unpbf(rp[p]);
            s += f.x * f.x + f.y * f.y;
        }
        atomicAdd((i < C) ? &g_qs2[row] : &g_ks2[row], s);
    }
}

// ---------------- gmk: attn normalize + mn mix + gating (12 blocks) ----------
__global__ void gmk_kernel(const float* __restrict__ mn_w,
                           const float* __restrict__ gating) {
    __shared__ float mn_t[32 * 64];  // [e][o]
    __shared__ float rk_s[32];
    const int tid = threadIdx.x;
    const int idx = blockIdx.x * 256 + tid;  // pair index
    const int dd = idx >> 4, pr = idx & 15, h = dd >> 5;
    for (int i = tid; i < 2048; i += 256) mn_t[(i & 31) * 64 + (i >> 5)] = mn_w[i];
    if (tid < 32) rk_s[tid] = 1.f / fmaxf(sqrtf(g_ks2[h * 32 + tid]), 1e-12f);
    __syncthreads();
    float rq = 1.f / fmaxf(sqrtf(g_qs2[dd]), 1e-12f);
    float a[32];
#pragma unroll
    for (int e = 0; e < 32; e++) a[e] = g_G[dd * 32 + e] * rq * rk_s[e];
    float s1a = 0.f, s1b = 0.f, s2a = 0.f, s2b = 0.f;
#pragma unroll
    for (int e = 0; e < 32; e++) {
        const float* mr = mn_t + e * 64;
        s1a += a[e] * mr[2 * pr];
        s1b += a[e] * mr[2 * pr + 1];
        s2a += a[e] * mr[32 + 2 * pr];
        s2b += a[e] * mr[33 + 2 * pr];
    }
    float g1 = __ldg(&gating[h]), g2 = __ldg(&gating[NH + h]);
    g_gmbf[idx] = packbf(g1 * s1a + g2 * s2a, g1 * s1b + g2 * s2b);
}

// ---------------- k4: mi(mma) + t=mi*v(bf16 in place) + softmax + proj -------
__global__ __launch_bounds__(512, 1) void k4(const float* __restrict__ cond,
                                             const float* __restrict__ x,
                                             float* __restrict__ out) {
    extern __shared__ unsigned sm[];
    unsigned* c_s  = sm;                 // 12800 u32: cond -> t(bf16) -> softmax
    unsigned* w_s  = sm + 12800;         // 3200
    unsigned* gm_s = sm + 12800 + 3200;  // 192*20
    const int tid = threadIdx.x, lane = tid & 31, warp = tid >> 5;
    const int gid = lane >> 2, tg = lane & 3;
    const int mb = (warp & 3) * 32, nb = (warp >> 2) * 48;
    const int p0 = blockIdx.x * TP;

    for (int i = tid; i < C * 16; i += 512) gm_s[(i >> 4) * 20 + (i & 15)] = g_gmbf[i];
    for (int c2 = warp; c2 < 96; c2 += 16) {
        int c = 2 * c2;
#pragma unroll
        for (int pb = 0; pb < 128; pb += 32) {
            float v0 = cond[(size_t)c * HW + p0 + pb + lane];
            float v1 = cond[(size_t)(c + 1) * HW + p0 + pb + lane];
            c_s[(pb + lane) * PXS + c2] = packbf(v0, v1);
        }
    }
    __syncthreads();

    // mi[px][ch] = sum_e cond[px][h*32+e] * gm[ch][e]
    float acc[2][6][4];
#pragma unroll
    for (int mt = 0; mt < 2; mt++)
#pragma unroll
        for (int nt = 0; nt < 6; nt++)
#pragma unroll
            for (int r = 0; r < 4; r++) acc[mt][nt][r] = 0.f;
#pragma unroll
    for (int kl = 0; kl < 2; kl++) {
        const int k2 = kl * 8;
        int hprev = -1;
        unsigned a[2][4];
#pragma unroll
        for (int nt = 0; nt < 6; nt++) {
            int h = (nb + nt * 8) >> 5;
            if (h != hprev) {
#pragma unroll
                for (int mt = 0; mt < 2; mt++) {
                    const unsigned* ab = c_s + (mb + mt * 16 + gid) * PXS + h * 16 + k2 + tg;
                    a[mt][0] = ab[0];
                    a[mt][1] = ab[8 * PXS];
                    a[mt][2] = ab[4];
                    a[mt][3] = ab[8 * PXS + 4];
                }
                hprev = h;
            }
            const unsigned* gp = gm_s + (nb + nt * 8 + gid) * 20 + k2 + tg;
            unsigned b0 = gp[0], b1 = gp[4];
#pragma unroll
            for (int mt = 0; mt < 2; mt++) mma_bf16(acc[mt][nt], a[mt], b0, b1);
        }
    }
    __syncthreads();   // everyone done reading cond before t overwrites c_s

    // t = mi * v  -> bf16x2 in place over c_s
    {
        const unsigned* vt = g_v + (size_t)blockIdx.x * (TP * 96);
#pragma unroll
        for (int mt = 0; mt < 2; mt++)
#pragma unroll
            for (int nt = 0; nt < 6; nt++) {
                int px = mb + mt * 16 + gid, cp = (nb + nt * 8) / 2 + tg;
                float2 v0 = unpbf(__ldg(&vt[px * 96 + cp]));
                float2 v1 = unpbf(__ldg(&vt[(px + 8) * 96 + cp]));
                c_s[px * PXS + cp]       = packbf(acc[mt][nt][0] * v0.x, acc[mt][nt][1] * v0.y);
                c_s[(px + 8) * PXS + cp] = packbf(acc[mt][nt][2] * v1.x, acc[mt][nt][3] * v1.y);
            }
    }
    __syncthreads();

    // softmax over head-dim (32 ch) per (px, head); in place bf16x2
    for (int task = tid; task < NH * TP; task += 512) {
        int px = task & 127, h = task >> 7;
        unsigned* row = c_s + px * PXS + h * 16;
        float e[32];
        float m = -1e30f;
#pragma unroll
        for (int j = 0; j < 16; j++) {
            float2 f = unpbf(row[j]);
            e[2 * j] = f.x; e[2 * j + 1] = f.y;
            m = fmaxf(m, fmaxf(f.x, f.y));
        }
        float s = 0.f;
#pragma unroll
        for (int d = 0; d < 32; d++) {
            e[d] = __expf(e[d] - m);
            s += e[d];
        }
        float r = 1.f / s;
#pragma unroll
        for (int j = 0; j < 16; j++) row[j] = packbf(e[2 * j] * r, e[2 * j + 1] * r);
    }

    // proj GEMM + residual
#pragma unroll
    for (int mt = 0; mt < 2; mt++)
#pragma unroll
        for (int nt = 0; nt < 6; nt++)
#pragma unroll
            for (int r = 0; r < 4; r++) acc[mt][nt][r] = 0.f;
    gemm_bf(c_s, w_s, g_wbf + 4 * MS, acc, tid);
#pragma unroll
    for (int mt = 0; mt < 2; mt++)
#pragma unroll
        for (int nt = 0; nt < 6; nt++) {
            int o = nb + nt * 8 + 2 * tg;
            size_t i00 = (size_t)o * HW + p0 + mb + mt * 16 + gid;
            out[i00]          = acc[mt][nt][0] + __ldg(&x[i00]);
            out[i00 + HW]     = acc[mt][nt][1] + __ldg(&x[i00 + HW]);
            out[i00 + 8]      = acc[mt][nt][2] + __ldg(&x[i00 + 8]);
            out[i00 + HW + 8] = acc[mt][nt][3] + __ldg(&x[i00 + HW + 8]);
        }
}

// ---------------- launch -----------------------------------------------------
extern "C" void kernel_launch(void* const* d_in, const int* in_sizes, int n_in,
                              void* d_out, int out_size) {
    const float* x      = (const float*)d_in[0];
    const float* cond   = (const float*)d_in[1];
    const float* ln_g   = (const float*)d_in[2];
    const float* ln_b   = (const float*)d_in[3];
    const float* pre_w  = (const float*)d_in[4];
    const float* pre_b  = (const float*)d_in[5];
    const float* qkv_w  = (const float*)d_in[6];
    const float* mn_w   = (const float*)d_in[7];
    const float* gating = (const float*)d_in[8];
    const float* proj_w = (const float*)d_in[9];
    float* out = (float*)d_out;

    const int SM12 = (13056 + 12800 + 13056 + 3200 + 640) * 4;  // 170,  ~171KB
    const int SM4  = (12800 + 3200 + 192 * 20) * 4;             // 79,360 B
    cudaFuncSetAttribute(k12, cudaFuncAttributeMaxDynamicSharedMemorySize, SM12);
    cudaFuncSetAttribute(k4,  cudaFuncAttributeMaxDynamicSharedMemorySize, SM4);

    prep_kernel<<<(5 * MS + 255) / 256, 256>>>(pre_w, qkv_w, proj_w);
    k12<<<HW / TP, 512, SM12>>>(x, ln_g, ln_b, pre_b);
    gmk_kernel<<<12, 256>>>(mn_w, gating);
    k4<<<HW / TP, 512, SM4>>>(cond, x, out);
}

// round 6
// speedup vs baseline: 1.5035x; 1.5035x over previous
#include <cuda_runtime.h>
#include <cuda_bf16.h>

#define HW 200704
#define C 192
#define TP 128
#define NH 6
#define D 32
#define PXS 100   // u32 stride for px-major bf16x2 tiles (96 ch-pairs + 4 pad)
#define WST 200   // u32 stride per k-pair row in weight chunk
#define WBUF 3200 // u32 per weight chunk buffer (16 rows x WST)
#define QS  136   // bf16 stride for ch-major q/k tiles
#define MS  (96 * 192)   // u32 per converted weight matrix

// ---------------- scratch ----------------------------------------------------
__device__ unsigned g_wbf[5 * MS];                    // pre,q,k,v,proj bf16x2 [cp][o]
__device__ unsigned g_v[(size_t)(HW / TP) * TP * 96]; // v tiles, px-major bf16x2
__device__ float    g_G[NH * D * D];
__device__ float    g_qs2[C];
__device__ float    g_ks2[C];
__device__ unsigned g_gmbf[C * 16];                   // gm bf16x2 pairs [ch][e/2]

// ---------------- helpers ----------------------------------------------------
__device__ __forceinline__ unsigned packbf(float a, float b) {
    __nv_bfloat162 p = __floats2bfloat162_rn(a, b);
    return *(unsigned*)&p;
}
__device__ __forceinline__ float2 unpbf(unsigned u) {
    __nv_bfloat162 p = *(__nv_bfloat162*)&u;
    return __bfloat1622float2(p);
}
__device__ __forceinline__ void mma_bf16(float d[4], const unsigned a[4],
                                         unsigned b0, unsigned b1) {
    asm volatile(
        "mma.sync.aligned.m16n8k16.row.col.f32.bf16.bf16.f32 "
        "{%0,%1,%2,%3},{%4,%5,%6,%7},{%8,%9},{%0,%1,%2,%3};\n"
        : "+f"(d[0]), "+f"(d[1]), "+f"(d[2]), "+f"(d[3])
        : "r"(a[0]), "r"(a[1]), "r"(a[2]), "r"(a[3]), "r"(b0), "r"(b1));
}

// async 16B-per-thread prefetch of one 16x192-u32 weight chunk (256 threads)
__device__ __forceinline__ void wchunk_prefetch(unsigned* wbuf,
                                                const unsigned* __restrict__ wg,
                                                int ch, int tid) {
#pragma unroll
    for (int r = 0; r < 3; r++) {
        int seg = tid + r * 256;
        int j = seg / 48, off = (seg - j * 48) * 4;
        unsigned ds = (unsigned)__cvta_generic_to_shared(wbuf + j * WST + off);
        asm volatile("cp.async.cg.shared.global [%0], [%1], 16;"
                     :: "r"(ds), "l"(wg + ch * 3072 + j * 192 + off));
    }
    asm volatile("cp.async.commit_group;" ::: "memory");
}

// bf16 GEMM over a px-major [128px][96 cpair] smem tile (stride PXS u32) with a
// pre-converted weight matrix double-buffered through w_s (2 x WBUF u32) via
// cp.async. 256 threads, warp grid 2Mx4N (warp tile 64px x 48ch). All threads
// must call; one __syncthreads per chunk.
__device__ __forceinline__ void gemm_bf_db(const unsigned* a_s, unsigned* w_s,
                                           const unsigned* __restrict__ wg,
                                           float acc[4][6][4], int tid) {
    const int lane = tid & 31, warp = tid >> 5;
    const int gid = lane >> 2, tg = lane & 3;
    const int mb = (warp & 1) * 64, nb = (warp >> 1) * 48;
    wchunk_prefetch(w_s, wg, 0, tid);
    for (int ch = 0; ch < 6; ch++) {
        asm volatile("cp.async.wait_group 0;" ::: "memory");
        __syncthreads();
        if (ch < 5) wchunk_prefetch(w_s + ((ch + 1) & 1) * WBUF, wg, ch + 1, tid);
        const unsigned* wb_base = w_s + (ch & 1) * WBUF;
#pragma unroll
        for (int kl = 0; kl < 2; kl++) {
            const int k2 = ch * 16 + kl * 8;
            unsigned a[4][4];
#pragma unroll
            for (int mt = 0; mt < 4; mt++) {
                const unsigned* ab = a_s + (mb + mt * 16 + gid) * PXS + k2 + tg;
                a[mt][0] = ab[0];
                a[mt][1] = ab[8 * PXS];
                a[mt][2] = ab[4];
                a[mt][3] = ab[8 * PXS + 4];
            }
#pragma unroll
            for (int nt = 0; nt < 6; nt++) {
                const unsigned* wb = wb_base + (kl * 8 + tg) * WST + nb + nt * 8 + gid;
                unsigned b0 = wb[0], b1 = wb[4 * WST];
#pragma unroll
                for (int mt = 0; mt < 4; mt++) mma_bf16(acc[mt][nt], a[mt], b0, b1);
            }
        }
    }
}

// ---------------- prep: convert weights to bf16x2 + zero accumulators --------
__global__ void prep_kernel(const float* __restrict__ pre_w,
                            const float* __restrict__ qkv_w,
                            const float* __restrict__ proj_w) {
    int idx = blockIdx.x * 256 + threadIdx.x;
    if (idx < 5 * MS) {
        int m = idx / MS, r = idx - m * MS;
        int cp = r / 192, o = r - cp * 192;
        const float* W = (m == 0) ? pre_w : (m < 4 ? qkv_w + (m - 1) * C * C : proj_w);
        g_wbf[idx] = packbf(W[o * C + 2 * cp], W[o * C + 2 * cp + 1]);
    }
    if (blockIdx.x == 0) {
        for (int i = threadIdx.x; i < NH * D * D; i += 256) g_G[i] = 0.f;
        if (threadIdx.x < C) {
            g_qs2[threadIdx.x] = 0.f;
            g_ks2[threadIdx.x] = 0.f;
        }
    }
}

// ---------------- k12: LN + pre + qkv + Gram (256 thr) -----------------------
__global__ __launch_bounds__(256, 1) void k12(const float* __restrict__ x,
                                              const float* __restrict__ lng,
                                              const float* __restrict__ lnb,
                                              const float* __restrict__ pre_b) {
    extern __shared__ unsigned sm[];
    unsigned* bufA = sm;                               // 13056 u32: x tile -> q_s
    unsigned* y_s  = sm + 13056;                       // 12800
    unsigned* kbuf = sm + 13056 + 12800;               // 13056: k_s
    unsigned* w_s  = sm + 13056 + 12800 + 13056;       // 6400 (double buffer)
    float* gb = (float*)(w_s + 2 * WBUF);              // g[192], b[192]
    float* mu = gb + 384;                              // 128
    float* rs = mu + 128;                              // 128
    const int tid = threadIdx.x, lane = tid & 31, warp = tid >> 5;
    const int gid = lane >> 2, tg = lane & 3;
    const int mb = (warp & 1) * 64, nb = (warp >> 1) * 48;
    const int p0 = blockIdx.x * TP;

    for (int i = tid; i < C; i += 256) {
        gb[i]       = lng[i];
        gb[192 + i] = lnb[i];
    }
    // x transpose into px-major bf16x2
    for (int c2 = warp; c2 < 96; c2 += 8) {
        int c = 2 * c2;
#pragma unroll
        for (int pb = 0; pb < 128; pb += 32) {
            float v0 = x[(size_t)c * HW + p0 + pb + lane];
            float v1 = x[(size_t)(c + 1) * HW + p0 + pb + lane];
            bufA[(pb + lane) * PXS + c2] = packbf(v0, v1);
        }
    }
    __syncthreads();
    // LN stats: warp per px row, lanes over channel pairs, shuffle reduce
    for (int px = warp; px < 128; px += 8) {
        float s = 0.f, s2 = 0.f;
        for (int c2 = lane; c2 < 96; c2 += 32) {
            float2 f = unpbf(bufA[px * PXS + c2]);
            s += f.x + f.y;
            s2 += f.x * f.x + f.y * f.y;
        }
#pragma unroll
        for (int o = 16; o; o >>= 1) {
            s  += __shfl_xor_sync(~0u, s, o);
            s2 += __shfl_xor_sync(~0u, s2, o);
        }
        if (lane == 0) {
            float m = s * (1.f / C), v = s2 * (1.f / C) - m * m;
            mu[px] = m;
            rs[px] = rsqrtf(v + 1e-5f);
        }
    }
    __syncthreads();
    // apply LN
    for (int px = warp; px < 128; px += 8) {
        float m = mu[px], r = rs[px];
        for (int c2 = lane; c2 < 96; c2 += 32) {
            float2 f = unpbf(bufA[px * PXS + c2]);
            f.x = (f.x - m) * r * gb[2 * c2]     + gb[192 + 2 * c2];
            f.y = (f.y - m) * r * gb[2 * c2 + 1] + gb[192 + 2 * c2 + 1];
            bufA[px * PXS + c2] = packbf(f.x, f.y);
        }
    }

    float acc[4][6][4];
    // ---- pre GEMM (bias init) ----
#pragma unroll
    for (int nt = 0; nt < 6; nt++) {
        int o = nb + nt * 8 + 2 * tg;
        float b0 = __ldg(&pre_b[o]), b1 = __ldg(&pre_b[o + 1]);
#pragma unroll
        for (int mt = 0; mt < 4; mt++) {
            acc[mt][nt][0] = b0; acc[mt][nt][1] = b1;
            acc[mt][nt][2] = b0; acc[mt][nt][3] = b1;
        }
    }
    gemm_bf_db(bufA, w_s, g_wbf, acc, tid);
#pragma unroll
    for (int mt = 0; mt < 4; mt++)
#pragma unroll
        for (int nt = 0; nt < 6; nt++) {
            int px = mb + mt * 16 + gid, cp = (nb + nt * 8) / 2 + tg;
            y_s[px * PXS + cp]       = packbf(acc[mt][nt][0], acc[mt][nt][1]);
            y_s[(px + 8) * PXS + cp] = packbf(acc[mt][nt][2], acc[mt][nt][3]);
        }
    // ---- q GEMM -> ch-major q_s (over bufA) ----
#pragma unroll
    for (int mt = 0; mt < 4; mt++)
#pragma unroll
        for (int nt = 0; nt < 6; nt++)
#pragma unroll
            for (int r = 0; r < 4; r++) acc[mt][nt][r] = 0.f;
    gemm_bf_db(y_s, w_s, g_wbf + MS, acc, tid);
    {
        __nv_bfloat16* q_s = (__nv_bfloat16*)bufA;
#pragma unroll
        for (int mt = 0; mt < 4; mt++)
#pragma unroll
            for (int nt = 0; nt < 6; nt++) {
                int o = nb + nt * 8 + 2 * tg, p = mb + mt * 16 + gid;
                q_s[o * QS + p]           = __float2bfloat16(acc[mt][nt][0]);
                q_s[(o + 1) * QS + p]     = __float2bfloat16(acc[mt][nt][1]);
                q_s[o * QS + p + 8]       = __float2bfloat16(acc[mt][nt][2]);
                q_s[(o + 1) * QS + p + 8] = __float2bfloat16(acc[mt][nt][3]);
            }
    }
    // ---- k GEMM -> ch-major k_s ----
#pragma unroll
    for (int mt = 0; mt < 4; mt++)
#pragma unroll
        for (int nt = 0; nt < 6; nt++)
#pragma unroll
            for (int r = 0; r < 4; r++) acc[mt][nt][r] = 0.f;
    gemm_bf_db(y_s, w_s, g_wbf + 2 * MS, acc, tid);
    {
        __nv_bfloat16* k_s = (__nv_bfloat16*)kbuf;
#pragma unroll
        for (int mt = 0; mt < 4; mt++)
#pragma unroll
            for (int nt = 0; nt < 6; nt++) {
                int o = nb + nt * 8 + 2 * tg, p = mb + mt * 16 + gid;
                k_s[o * QS + p]           = __float2bfloat16(acc[mt][nt][0]);
                k_s[(o + 1) * QS + p]     = __float2bfloat16(acc[mt][nt][1]);
                k_s[o * QS + p + 8]       = __float2bfloat16(acc[mt][nt][2]);
                k_s[(o + 1) * QS + p + 8] = __float2bfloat16(acc[mt][nt][3]);
            }
    }
    // ---- v GEMM -> DRAM bf16x2 px-major ----
#pragma unroll
    for (int mt = 0; mt < 4; mt++)
#pragma unroll
        for (int nt = 0; nt < 6; nt++)
#pragma unroll
            for (int r = 0; r < 4; r++) acc[mt][nt][r] = 0.f;
    gemm_bf_db(y_s, w_s, g_wbf + 3 * MS, acc, tid);
    {
        unsigned* vt = g_v + (size_t)blockIdx.x * (TP * 96);
#pragma unroll
        for (int mt = 0; mt < 4; mt++)
#pragma unroll
            for (int nt = 0; nt < 6; nt++) {
                int px = mb + mt * 16 + gid, cp = (nb + nt * 8) / 2 + tg;
                vt[px * 96 + cp]       = packbf(acc[mt][nt][0], acc[mt][nt][1]);
                vt[(px + 8) * 96 + cp] = packbf(acc[mt][nt][2], acc[mt][nt][3]);
            }
    }
    __syncthreads();

    // ---- Gram per head via bf16 mma over 128 px (warp w == head w) ----------
    if (warp < 6) {
        const __nv_bfloat16* q_s = (const __nv_bfloat16*)bufA;
        const __nv_bfloat16* k_s = (const __nv_bfloat16*)kbuf;
        const int h = warp;
        float dG[2][4][4];
#pragma unroll
        for (int mt = 0; mt < 2; mt++)
#pragma unroll
            for (int nt = 0; nt < 4; nt++)
#pragma unroll
                for (int r = 0; r < 4; r++) dG[mt][nt][r] = 0.f;
        for (int kc = 0; kc < TP; kc += 16) {
            unsigned a[2][4];
#pragma unroll
            for (int mt = 0; mt < 2; mt++) {
                const __nv_bfloat16* ab = q_s + (h * 32 + mt * 16 + gid) * QS + kc + 2 * tg;
                a[mt][0] = *(const unsigned*)(ab);
                a[mt][1] = *(const unsigned*)(ab + 8 * QS);
                a[mt][2] = *(const unsigned*)(ab + 8);
                a[mt][3] = *(const unsigned*)(ab + 8 * QS + 8);
            }
#pragma unroll
            for (int nt = 0; nt < 4; nt++) {
                const __nv_bfloat16* bb = k_s + (h * 32 + nt * 8 + gid) * QS + kc + 2 * tg;
                unsigned b0 = *(const unsigned*)(bb);
                unsigned b1 = *(const unsigned*)(bb + 8);
#pragma unroll
                for (int mt = 0; mt < 2; mt++) mma_bf16(dG[mt][nt], a[mt], b0, b1);
            }
        }
#pragma unroll
        for (int mt = 0; mt < 2; mt++)
#pragma unroll
            for (int nt = 0; nt < 4; nt++) {
                int r0 = h * 32 + mt * 16 + gid, c0 = nt * 8 + 2 * tg;
                atomicAdd(&g_G[r0 * 32 + c0],           dG[mt][nt][0]);
                atomicAdd(&g_G[r0 * 32 + c0 + 1],       dG[mt][nt][1]);
                atomicAdd(&g_G[(r0 + 8) * 32 + c0],     dG[mt][nt][2]);
                atomicAdd(&g_G[(r0 + 8) * 32 + c0 + 1], dG[mt][nt][3]);
            }
    }
    // squared norms from the same bf16 values
    for (int i = tid; i < 2 * C; i += 256) {
        const unsigned* arr = (i < C) ? bufA : kbuf;
        int row = (i < C) ? i : i - C;
        const unsigned* rp = arr + row * (QS / 2);
        float s = 0.f;
        for (int p = 0; p < 64; p++) {
            float2 f = unpbf(rp[p]);
            s += f.x * f.x + f.y * f.y;
        }
        atomicAdd((i < C) ? &g_qs2[row] : &g_ks2[row], s);
    }
}

// ---------------- gmk: attn normalize + mn mix + gating (12 blocks) ----------
__global__ void gmk_kernel(const float* __restrict__ mn_w,
                           const float* __restrict__ gating) {
    __shared__ float mn_t[32 * 64];  // [e][o]
    __shared__ float rk_s[32];
    const int tid = threadIdx.x;
    const int idx = blockIdx.x * 256 + tid;  // pair index
    const int dd = idx >> 4, pr = idx & 15, h = dd >> 5;
    for (int i = tid; i < 2048; i += 256) mn_t[(i & 31) * 64 + (i >> 5)] = mn_w[i];
    if (tid < 32) rk_s[tid] = 1.f / fmaxf(sqrtf(g_ks2[h * 32 + tid]), 1e-12f);
    __syncthreads();
    float rq = 1.f / fmaxf(sqrtf(g_qs2[dd]), 1e-12f);
    float a[32];
#pragma unroll
    for (int e = 0; e < 32; e++) a[e] = g_G[dd * 32 + e] * rq * rk_s[e];
    float s1a = 0.f, s1b = 0.f, s2a = 0.f, s2b = 0.f;
#pragma unroll
    for (int e = 0; e < 32; e++) {
        const float* mr = mn_t + e * 64;
        s1a += a[e] * mr[2 * pr];
        s1b += a[e] * mr[2 * pr + 1];
        s2a += a[e] * mr[32 + 2 * pr];
        s2b += a[e] * mr[33 + 2 * pr];
    }
    float g1 = __ldg(&gating[h]), g2 = __ldg(&gating[NH + h]);
    g_gmbf[idx] = packbf(g1 * s1a + g2 * s2a, g1 * s1b + g2 * s2b);
}

// ---------------- k4: mi(mma) + t=mi*v(bf16 in place) + softmax + proj -------
__global__ __launch_bounds__(256, 2) void k4(const float* __restrict__ cond,
                                             const float* __restrict__ x,
                                             float* __restrict__ out) {
    extern __shared__ unsigned sm[];
    unsigned* c_s  = sm;                 // 12800 u32: cond -> t(bf16) -> softmax
    unsigned* w_s  = sm + 12800;         // 6400 (double buffer)
    unsigned* gm_s = sm + 12800 + 6400;  // 192*20
    const int tid = threadIdx.x, lane = tid & 31, warp = tid >> 5;
    const int gid = lane >> 2, tg = lane & 3;
    const int mb = (warp & 1) * 64, nb = (warp >> 1) * 48;
    const int p0 = blockIdx.x * TP;

    for (int i = tid; i < C * 16; i += 256) gm_s[(i >> 4) * 20 + (i & 15)] = g_gmbf[i];
    for (int c2 = warp; c2 < 96; c2 += 8) {
        int c = 2 * c2;
#pragma unroll
        for (int pb = 0; pb < 128; pb += 32) {
            float v0 = cond[(size_t)c * HW + p0 + pb + lane];
            float v1 = cond[(size_t)(c + 1) * HW + p0 + pb + lane];
            c_s[(pb + lane) * PXS + c2] = packbf(v0, v1);
        }
    }
    __syncthreads();

    // mi[px][ch] = sum_e cond[px][h*32+e] * gm[ch][e]
    float acc[4][6][4];
#pragma unroll
    for (int mt = 0; mt < 4; mt++)
#pragma unroll
        for (int nt = 0; nt < 6; nt++)
#pragma unroll
            for (int r = 0; r < 4; r++) acc[mt][nt][r] = 0.f;
#pragma unroll
    for (int kl = 0; kl < 2; kl++) {
        const int k2 = kl * 8;
        int hprev = -1;
        unsigned a[4][4];
#pragma unroll
        for (int nt = 0; nt < 6; nt++) {
            int h = (nb + nt * 8) >> 5;
            if (h != hprev) {
#pragma unroll
                for (int mt = 0; mt < 4; mt++) {
                    const unsigned* ab = c_s + (mb + mt * 16 + gid) * PXS + h * 16 + k2 + tg;
                    a[mt][0] = ab[0];
                    a[mt][1] = ab[8 * PXS];
                    a[mt][2] = ab[4];
                    a[mt][3] = ab[8 * PXS + 4];
                }
                hprev = h;
            }
            const unsigned* gp = gm_s + (nb + nt * 8 + gid) * 20 + k2 + tg;
            unsigned b0 = gp[0], b1 = gp[4];
#pragma unroll
            for (int mt = 0; mt < 4; mt++) mma_bf16(acc[mt][nt], a[mt], b0, b1);
        }
    }
    __syncthreads();   // everyone done reading cond before t overwrites c_s

    // t = mi * v  -> bf16x2 in place over c_s
    {
        const unsigned* vt = g_v + (size_t)blockIdx.x * (TP * 96);
#pragma unroll
        for (int mt = 0; mt < 4; mt++)
#pragma unroll
            for (int nt = 0; nt < 6; nt++) {
                int px = mb + mt * 16 + gid, cp = (nb + nt * 8) / 2 + tg;
                float2 v0 = unpbf(__ldg(&vt[px * 96 + cp]));
                float2 v1 = unpbf(__ldg(&vt[(px + 8) * 96 + cp]));
                c_s[px * PXS + cp]       = packbf(acc[mt][nt][0] * v0.x, acc[mt][nt][1] * v0.y);
                c_s[(px + 8) * PXS + cp] = packbf(acc[mt][nt][2] * v1.x, acc[mt][nt][3] * v1.y);
            }
    }
    __syncthreads();

    // softmax over head-dim (32 ch) per (px, head); in place bf16x2
#pragma unroll
    for (int k = 0; k < 3; k++) {
        int task = tid + k * 256;
        int px = task & 127, h = task >> 7;
        unsigned* row = c_s + px * PXS + h * 16;
        float e[32];
        float m = -1e30f;
#pragma unroll
        for (int j = 0; j < 16; j++) {
            float2 f = unpbf(row[j]);
            e[2 * j] = f.x; e[2 * j + 1] = f.y;
            m = fmaxf(m, fmaxf(f.x, f.y));
        }
        float s = 0.f;
#pragma unroll
        for (int d = 0; d < 32; d++) {
            e[d] = __expf(e[d] - m);
            s += e[d];
        }
        float r = 1.f / s;
#pragma unroll
        for (int j = 0; j < 16; j++) row[j] = packbf(e[2 * j] * r, e[2 * j + 1] * r);
    }

    // proj GEMM + residual (db gemm's internal barrier orders softmax writes)
#pragma unroll
    for (int mt = 0; mt < 4; mt++)
#pragma unroll
        for (int nt = 0; nt < 6; nt++)
#pragma unroll
            for (int r = 0; r < 4; r++) acc[mt][nt][r] = 0.f;
    gemm_bf_db(c_s, w_s, g_wbf + 4 * MS, acc, tid);
#pragma unroll
    for (int mt = 0; mt < 4; mt++)
#pragma unroll
        for (int nt = 0; nt < 6; nt++) {
            int o = nb + nt * 8 + 2 * tg;
            size_t i00 = (size_t)o * HW + p0 + mb + mt * 16 + gid;
            out[i00]          = acc[mt][nt][0] + __ldg(&x[i00]);
            out[i00 + HW]     = acc[mt][nt][1] + __ldg(&x[i00 + HW]);
            out[i00 + 8]      = acc[mt][nt][2] + __ldg(&x[i00 + 8]);
            out[i00 + HW + 8] = acc[mt][nt][3] + __ldg(&x[i00 + HW + 8]);
        }
}

// ---------------- launch -----------------------------------------------------
extern "C" void kernel_launch(void* const* d_in, const int* in_sizes, int n_in,
                              void* d_out, int out_size) {
    const float* x      = (const float*)d_in[0];
    const float* cond   = (const float*)d_in[1];
    const float* ln_g   = (const float*)d_in[2];
    const float* ln_b   = (const float*)d_in[3];
    const float* pre_w  = (const float*)d_in[4];
    const float* pre_b  = (const float*)d_in[5];
    const float* qkv_w  = (const float*)d_in[6];
    const float* mn_w   = (const float*)d_in[7];
    const float* gating = (const float*)d_in[8];
    const float* proj_w = (const float*)d_in[9];
    float* out = (float*)d_out;

    const int SM12 = (13056 + 12800 + 13056 + 2 * WBUF + 640) * 4;  // 183808 B
    const int SM4  = (12800 + 2 * WBUF + 192 * 20) * 4;             // 92160 B
    cudaFuncSetAttribute(k12, cudaFuncAttributeMaxDynamicSharedMemorySize, SM12);
    cudaFuncSetAttribute(k4,  cudaFuncAttributeMaxDynamicSharedMemorySize, SM4);

    prep_kernel<<<(5 * MS + 255) / 256, 256>>>(pre_w, qkv_w, proj_w);
    k12<<<HW / TP, 256, SM12>>>(x, ln_g, ln_b, pre_b);
    gmk_kernel<<<12, 256>>>(mn_w, gating);
    k4<<<HW / TP, 256, SM4>>>(cond, x, out);
}

// round 9
// speedup vs baseline: 1.6810x; 1.1181x over previous
#include <cuda_runtime.h>
#include <cuda_bf16.h>

#define HW 200704
#define C 192
#define NH 6
#define D 32
#define PXS 100    // u32 stride for px-major bf16x2 tiles (96 ch-pairs + 4 pad)
#define WST 200    // u32 stride per k-pair row in weight chunk
#define WBUF 3200  // u32 per weight chunk buffer (16 rows x WST)
#define MS  (96 * 192)   // u32 per converted weight matrix

// k12 tile: 64 px. k4 tile: 128 px.
#define TPA 64
#define QSA 72     // bf16 stride for ch-major q/k tiles (64 px + 8 pad)
#define TPB 128

// ---------------- scratch ----------------------------------------------------
__device__ unsigned g_wbf[5 * MS];                 // pre,q,k,v,proj bf16x2 [cp][o]
__device__ unsigned g_v[(size_t)HW * 96];          // v, px-major bf16x2 (global px)
__device__ float    g_G[NH * D * D];
__device__ float    g_qs2[C];
__device__ float    g_ks2[C];
__device__ unsigned g_gmbf[C * 16];                // gm bf16x2 pairs [ch][e/2]

// ---------------- helpers ----------------------------------------------------
__device__ __forceinline__ unsigned packbf(float a, float b) {
    __nv_bfloat162 p = __floats2bfloat162_rn(a, b);
    return *(unsigned*)&p;
}
__device__ __forceinline__ float2 unpbf(unsigned u) {
    __nv_bfloat162 p = *(__nv_bfloat162*)&u;
    return __bfloat1622float2(p);
}
__device__ __forceinline__ void mma_bf16(float d[4], const unsigned a[4],
                                         unsigned b0, unsigned b1) {
    asm volatile(
        "mma.sync.aligned.m16n8k16.row.col.f32.bf16.bf16.f32 "
        "{%0,%1,%2,%3},{%4,%5,%6,%7},{%8,%9},{%0,%1,%2,%3};\n"
        : "+f"(d[0]), "+f"(d[1]), "+f"(d[2]), "+f"(d[3])
        : "r"(a[0]), "r"(a[1]), "r"(a[2]), "r"(a[3]), "r"(b0), "r"(b1));
}

// async 16B-per-thread prefetch of one 16x192-u32 weight chunk (256 threads)
__device__ __forceinline__ void wchunk_prefetch(unsigned* wbuf,
                                                const unsigned* __restrict__ wg,
                                                int ch, int tid) {
#pragma unroll
    for (int r = 0; r < 3; r++) {
        int seg = tid + r * 256;
        int j = seg / 48, off = (seg - j * 48) * 4;
        unsigned ds = (unsigned)__cvta_generic_to_shared(wbuf + j * WST + off);
        asm volatile("cp.async.cg.shared.global [%0], [%1], 16;"
                     :: "r"(ds), "l"(wg + ch * 3072 + j * 192 + off));
    }
    asm volatile("cp.async.commit_group;" ::: "memory");
}

// -------- k12 GEMM: 64px tile, warp grid 2Mx4N (warp tile 32px x 48ch) -------
__device__ __forceinline__ void gemm_db64(const unsigned* a_s, unsigned* w_s,
                                          const unsigned* __restrict__ wg,
                                          float acc[2][6][4], int tid) {
    const int lane = tid & 31, warp = tid >> 5;
    const int gid = lane >> 2, tg = lane & 3;
    const int mb = (warp & 1) * 32, nb = (warp >> 1) * 48;
    wchunk_prefetch(w_s, wg, 0, tid);
    for (int ch = 0; ch < 6; ch++) {
        asm volatile("cp.async.wait_group 0;" ::: "memory");
        __syncthreads();
        if (ch < 5) wchunk_prefetch(w_s + ((ch + 1) & 1) * WBUF, wg, ch + 1, tid);
        const unsigned* wb_base = w_s + (ch & 1) * WBUF;
#pragma unroll
        for (int kl = 0; kl < 2; kl++) {
            const int k2 = ch * 16 + kl * 8;
            unsigned a[2][4];
#pragma unroll
            for (int mt = 0; mt < 2; mt++) {
                const unsigned* ab = a_s + (mb + mt * 16 + gid) * PXS + k2 + tg;
                a[mt][0] = ab[0];
                a[mt][1] = ab[8 * PXS];
                a[mt][2] = ab[4];
                a[mt][3] = ab[8 * PXS + 4];
            }
#pragma unroll
            for (int nt = 0; nt < 6; nt++) {
                const unsigned* wb = wb_base + (kl * 8 + tg) * WST + nb + nt * 8 + gid;
                unsigned b0 = wb[0], b1 = wb[4 * WST];
#pragma unroll
                for (int mt = 0; mt < 2; mt++) mma_bf16(acc[mt][nt], a[mt], b0, b1);
            }
        }
    }
}

// -------- k4 GEMM: 128px tile, warp grid 2Mx4N (warp tile 64px x 48ch) -------
__device__ __forceinline__ void gemm_db128(const unsigned* a_s, unsigned* w_s,
                                           const unsigned* __restrict__ wg,
                                           float acc[4][6][4], int tid) {
    const int lane = tid & 31, warp = tid >> 5;
    const int gid = lane >> 2, tg = lane & 3;
    const int mb = (warp & 1) * 64, nb = (warp >> 1) * 48;
    wchunk_prefetch(w_s, wg, 0, tid);
    for (int ch = 0; ch < 6; ch++) {
        asm volatile("cp.async.wait_group 0;" ::: "memory");
        __syncthreads();
        if (ch < 5) wchunk_prefetch(w_s + ((ch + 1) & 1) * WBUF, wg, ch + 1, tid);
        const unsigned* wb_base = w_s + (ch & 1) * WBUF;
#pragma unroll
        for (int kl = 0; kl < 2; kl++) {
            const int k2 = ch * 16 + kl * 8;
            unsigned a[4][4];
#pragma unroll
            for (int mt = 0; mt < 4; mt++) {
                const unsigned* ab = a_s + (mb + mt * 16 + gid) * PXS + k2 + tg;
                a[mt][0] = ab[0];
                a[mt][1] = ab[8 * PXS];
                a[mt][2] = ab[4];
                a[mt][3] = ab[8 * PXS + 4];
            }
#pragma unroll
            for (int nt = 0; nt < 6; nt++) {
                const unsigned* wb = wb_base + (kl * 8 + tg) * WST + nb + nt * 8 + gid;
                unsigned b0 = wb[0], b1 = wb[4 * WST];
#pragma unroll
                for (int mt = 0; mt < 4; mt++) mma_bf16(acc[mt][nt], a[mt], b0, b1);
            }
        }
    }
}

// ---------------- prep: convert weights to bf16x2 + zero accumulators --------
__global__ void prep_kernel(const float* __restrict__ pre_w,
                            const float* __restrict__ qkv_w,
                            const float* __restrict__ proj_w) {
    int idx = blockIdx.x * 256 + threadIdx.x;
    if (idx < 5 * MS) {
        int m = idx / MS, r = idx - m * MS;
        int cp = r / 192, o = r - cp * 192;
        const float* W = (m == 0) ? pre_w : (m < 4 ? qkv_w + (m - 1) * C * C : proj_w);
        g_wbf[idx] = packbf(W[o * C + 2 * cp], W[o * C + 2 * cp + 1]);
    }
    if (blockIdx.x == 0) {
        for (int i = threadIdx.x; i < NH * D * D; i += 256) g_G[i] = 0.f;
        if (threadIdx.x < C) {
            g_qs2[threadIdx.x] = 0.f;
            g_ks2[threadIdx.x] = 0.f;
        }
    }
}

// ---------------- k12: LN + pre + qkv + Gram (64px tile, 2 CTA/SM) -----------
__global__ __launch_bounds__(256, 2) void k12(const float* __restrict__ x,
                                              const float* __restrict__ lng,
                                              const float* __restrict__ lnb,
                                              const float* __restrict__ pre_b) {
    extern __shared__ unsigned sm[];
    unsigned* bufA = sm;                         // 6912 u32: x tile -> q_s
    unsigned* y_s  = sm + 6912;                  // 6400
    unsigned* kbuf = sm + 6912 + 6400;           // 6912: k_s
    unsigned* w_s  = sm + 6912 + 6400 + 6912;    // 6400 (double buffer)
    float* gb = (float*)(w_s + 2 * WBUF);        // g[192], b[192]
    float* mu = gb + 384;                        // 64
    float* rs = mu + 64;                         // 64
    const int tid = threadIdx.x, lane = tid & 31, warp = tid >> 5;
    const int gid = lane >> 2, tg = lane & 3;
    const int mb = (warp & 1) * 32, nb = (warp >> 1) * 48;
    const int p0 = blockIdx.x * TPA;

    for (int i = tid; i < C; i += 256) {
        gb[i]       = lng[i];
        gb[192 + i] = lnb[i];
    }
    // x transpose into px-major bf16x2
    for (int c2 = warp; c2 < 96; c2 += 8) {
        int c = 2 * c2;
#pragma unroll
        for (int pb = 0; pb < TPA; pb += 32) {
            float v0 = x[(size_t)c * HW + p0 + pb + lane];
            float v1 = x[(size_t)(c + 1) * HW + p0 + pb + lane];
            bufA[(pb + lane) * PXS + c2] = packbf(v0, v1);
        }
    }
    __syncthreads();
    // LN stats: warp per px row, lanes over channel pairs, shuffle reduce
    for (int px = warp; px < TPA; px += 8) {
        float s = 0.f, s2 = 0.f;
        for (int c2 = lane; c2 < 96; c2 += 32) {
            float2 f = unpbf(bufA[px * PXS + c2]);
            s += f.x + f.y;
            s2 += f.x * f.x + f.y * f.y;
        }
#pragma unroll
        for (int o = 16; o; o >>= 1) {
            s  += __shfl_xor_sync(~0u, s, o);
            s2 += __shfl_xor_sync(~0u, s2, o);
        }
        if (lane == 0) {
            float m = s * (1.f / C), v = s2 * (1.f / C) - m * m;
            mu[px] = m;
            rs[px] = rsqrtf(v + 1e-5f);
        }
    }
    __syncthreads();
    // apply LN
    for (int px = warp; px < TPA; px += 8) {
        float m = mu[px], r = rs[px];
        for (int c2 = lane; c2 < 96; c2 += 32) {
            float2 f = unpbf(bufA[px * PXS + c2]);
            f.x = (f.x - m) * r * gb[2 * c2]     + gb[192 + 2 * c2];
            f.y = (f.y - m) * r * gb[2 * c2 + 1] + gb[192 + 2 * c2 + 1];
            bufA[px * PXS + c2] = packbf(f.x, f.y);
        }
    }

    float acc[2][6][4];
    // ---- pre GEMM (bias init) ----
#pragma unroll
    for (int nt = 0; nt < 6; nt++) {
        int o = nb + nt * 8 + 2 * tg;
        float b0 = __ldg(&pre_b[o]), b1 = __ldg(&pre_b[o + 1]);
#pragma unroll
        for (int mt = 0; mt < 2; mt++) {
            acc[mt][nt][0] = b0; acc[mt][nt][1] = b1;
            acc[mt][nt][2] = b0; acc[mt][nt][3] = b1;
        }
    }
    gemm_db64(bufA, w_s, g_wbf, acc, tid);
#pragma unroll
    for (int mt = 0; mt < 2; mt++)
#pragma unroll
        for (int nt = 0; nt < 6; nt++) {
            int px = mb + mt * 16 + gid, cp = (nb + nt * 8) / 2 + tg;
            y_s[px * PXS + cp]       = packbf(acc[mt][nt][0], acc[mt][nt][1]);
            y_s[(px + 8) * PXS + cp] = packbf(acc[mt][nt][2], acc[mt][nt][3]);
        }
    // ---- q GEMM -> ch-major q_s (over bufA) ----
#pragma unroll
    for (int mt = 0; mt < 2; mt++)
#pragma unroll
        for (int nt = 0; nt < 6; nt++)
#pragma unroll
            for (int r = 0; r < 4; r++) acc[mt][nt][r] = 0.f;
    gemm_db64(y_s, w_s, g_wbf + MS, acc, tid);
    {
        __nv_bfloat16* q_s = (__nv_bfloat16*)bufA;
#pragma unroll
        for (int mt = 0; mt < 2; mt++)
#pragma unroll
            for (int nt = 0; nt < 6; nt++) {
                int o = nb + nt * 8 + 2 * tg, p = mb + mt * 16 + gid;
                q_s[o * QSA + p]           = __float2bfloat16(acc[mt][nt][0]);
                q_s[(o + 1) * QSA + p]     = __float2bfloat16(acc[mt][nt][1]);
                q_s[o * QSA + p + 8]       = __float2bfloat16(acc[mt][nt][2]);
                q_s[(o + 1) * QSA + p + 8] = __float2bfloat16(acc[mt][nt][3]);
            }
    }
    // ---- k GEMM -> ch-major k_s ----
#pragma unroll
    for (int mt = 0; mt < 2; mt++)
#pragma unroll
        for (int nt = 0; nt < 6; nt++)
#pragma unroll
            for (int r = 0; r < 4; r++) acc[mt][nt][r] = 0.f;
    gemm_db64(y_s, w_s, g_wbf + 2 * MS, acc, tid);
    {
        __nv_bfloat16* k_s = (__nv_bfloat16*)kbuf;
#pragma unroll
        for (int mt = 0; mt < 2; mt++)
#pragma unroll
            for (int nt = 0; nt < 6; nt++) {
                int o = nb + nt * 8 + 2 * tg, p = mb + mt * 16 + gid;
                k_s[o * QSA + p]           = __float2bfloat16(acc[mt][nt][0]);
                k_s[(o + 1) * QSA + p]     = __float2bfloat16(acc[mt][nt][1]);
                k_s[o * QSA + p + 8]       = __float2bfloat16(acc[mt][nt][2]);
                k_s[(o + 1) * QSA + p + 8] = __float2bfloat16(acc[mt][nt][3]);
            }
    }
    // ---- v GEMM -> DRAM bf16x2 px-major (global px index) ----
#pragma unroll
    for (int mt = 0; mt < 2; mt++)
#pragma unroll
        for (int nt = 0; nt < 6; nt++)
#pragma unroll
            for (int r = 0; r < 4; r++) acc[mt][nt][r] = 0.f;
    gemm_db64(y_s, w_s, g_wbf + 3 * MS, acc, tid);
#pragma unroll
    for (int mt = 0; mt < 2; mt++)
#pragma unroll
        for (int nt = 0; nt < 6; nt++) {
            int px = mb + mt * 16 + gid, cp = (nb + nt * 8) / 2 + tg;
            g_v[(size_t)(p0 + px) * 96 + cp]     = packbf(acc[mt][nt][0], acc[mt][nt][1]);
            g_v[(size_t)(p0 + px + 8) * 96 + cp] = packbf(acc[mt][nt][2], acc[mt][nt][3]);
        }
    __syncthreads();

    // ---- Gram per head via bf16 mma over 64 px (warp w == head w) -----------
    if (warp < 6) {
        const __nv_bfloat16* q_s = (const __nv_bfloat16*)bufA;
        const __nv_bfloat16* k_s = (const __nv_bfloat16*)kbuf;
        const int h = warp;
        float dG[2][4][4];
#pragma unroll
        for (int mt = 0; mt < 2; mt++)
#pragma unroll
            for (int nt = 0; nt < 4; nt++)
#pragma unroll
                for (int r = 0; r < 4; r++) dG[mt][nt][r] = 0.f;
#pragma unroll
        for (int kc = 0; kc < TPA; kc += 16) {
            unsigned a[2][4];
#pragma unroll
            for (int mt = 0; mt < 2; mt++) {
                const __nv_bfloat16* ab = q_s + (h * 32 + mt * 16 + gid) * QSA + kc + 2 * tg;
                a[mt][0] = *(const unsigned*)(ab);
                a[mt][1] = *(const unsigned*)(ab + 8 * QSA);
                a[mt][2] = *(const unsigned*)(ab + 8);
                a[mt][3] = *(const unsigned*)(ab + 8 * QSA + 8);
            }
#pragma unroll
            for (int nt = 0; nt < 4; nt++) {
                const __nv_bfloat16* bb = k_s + (h * 32 + nt * 8 + gid) * QSA + kc + 2 * tg;
                unsigned b0 = *(const unsigned*)(bb);
                unsigned b1 = *(const unsigned*)(bb + 8);
#pragma unroll
                for (int mt = 0; mt < 2; mt++) mma_bf16(dG[mt][nt], a[mt], b0, b1);
            }
        }
#pragma unroll
        for (int mt = 0; mt < 2; mt++)
#pragma unroll
            for (int nt = 0; nt < 4; nt++) {
                int r0 = h * 32 + mt * 16 + gid, c0 = nt * 8 + 2 * tg;
                atomicAdd(&g_G[r0 * 32 + c0],           dG[mt][nt][0]);
                atomicAdd(&g_G[r0 * 32 + c0 + 1],       dG[mt][nt][1]);
                atomicAdd(&g_G[(r0 + 8) * 32 + c0],     dG[mt][nt][2]);
                atomicAdd(&g_G[(r0 + 8) * 32 + c0 + 1], dG[mt][nt][3]);
            }
    }
    // squared norms from the same bf16 values
    for (int i = tid; i < 2 * C; i += 256) {
        const unsigned* arr = (i < C) ? bufA : kbuf;
        int row = (i < C) ? i : i - C;
        const unsigned* rp = arr + row * (QSA / 2);
        float s = 0.f;
#pragma unroll
        for (int p = 0; p < TPA / 2; p++) {
            float2 f = unpbf(rp[p]);
            s += f.x * f.x + f.y * f.y;
        }
        atomicAdd((i < C) ? &g_qs2[row] : &g_ks2[row], s);
    }
}

// ---------------- gmk: attn normalize + mn mix + gating (12 blocks) ----------
__global__ void gmk_kernel(const float* __restrict__ mn_w,
                           const float* __restrict__ gating) {
    __shared__ float mn_t[32 * 64];  // [e][o]
    __shared__ float rk_s[32];
    const int tid = threadIdx.x;
    const int idx = blockIdx.x * 256 + tid;  // pair index
    const int dd = idx >> 4, pr = idx & 15, h = dd >> 5;
    for (int i = tid; i < 2048; i += 256) mn_t[(i & 31) * 64 + (i >> 5)] = mn_w[i];
    if (tid < 32) rk_s[tid] = 1.f / fmaxf(sqrtf(g_ks2[h * 32 + tid]), 1e-12f);
    __syncthreads();
    float rq = 1.f / fmaxf(sqrtf(g_qs2[dd]), 1e-12f);
    float a[32];
#pragma unroll
    for (int e = 0; e < 32; e++) a[e] = g_G[dd * 32 + e] * rq * rk_s[e];
    float s1a = 0.f, s1b = 0.f, s2a = 0.f, s2b = 0.f;
#pragma unroll
    for (int e = 0; e < 32; e++) {
        const float* mr = mn_t + e * 64;
        s1a += a[e] * mr[2 * pr];
        s1b += a[e] * mr[2 * pr + 1];
        s2a += a[e] * mr[32 + 2 * pr];
        s2b += a[e] * mr[33 + 2 * pr];
    }
    float g1 = __ldg(&gating[h]), g2 = __ldg(&gating[NH + h]);
    g_gmbf[idx] = packbf(g1 * s1a + g2 * s2a, g1 * s1b + g2 * s2b);
}

// ---------------- k4: mi(mma) + t=mi*v(bf16 in place) + softmax + proj -------
__global__ __launch_bounds__(256, 2) void k4(const float* __restrict__ cond,
                                             const float* __restrict__ x,
                                             float* __restrict__ out) {
    extern __shared__ unsigned sm[];
    unsigned* c_s  = sm;                 // 12800 u32: cond -> t(bf16) -> softmax
    unsigned* w_s  = sm + 12800;         // 6400 (double buffer)
    unsigned* gm_s = sm + 12800 + 6400;  // 192*20
    const int tid = threadIdx.x, lane = tid & 31, warp = tid >> 5;
    const int gid = lane >> 2, tg = lane & 3;
    const int mb = (warp & 1) * 64, nb = (warp >> 1) * 48;
    const int p0 = blockIdx.x * TPB;

    for (int i = tid; i < C * 16; i += 256) gm_s[(i >> 4) * 20 + (i & 15)] = g_gmbf[i];
    for (int c2 = warp; c2 < 96; c2 += 8) {
        int c = 2 * c2;
#pragma unroll
        for (int pb = 0; pb < TPB; pb += 32) {
            float v0 = cond[(size_t)c * HW + p0 + pb + lane];
            float v1 = cond[(size_t)(c + 1) * HW + p0 + pb + lane];
            c_s[(pb + lane) * PXS + c2] = packbf(v0, v1);
        }
    }
    __syncthreads();

    // mi[px][ch] = sum_e cond[px][h*32+e] * gm[ch][e]
    float acc[4][6][4];
#pragma unroll
    for (int mt = 0; mt < 4; mt++)
#pragma unroll
        for (int nt = 0; nt < 6; nt++)
#pragma unroll
            for (int r = 0; r < 4; r++) acc[mt][nt][r] = 0.f;
#pragma unroll
    for (int kl = 0; kl < 2; kl++) {
        const int k2 = kl * 8;
        int hprev = -1;
        unsigned a[4][4];
#pragma unroll
        for (int nt = 0; nt < 6; nt++) {
            int h = (nb + nt * 8) >> 5;
            if (h != hprev) {
#pragma unroll
                for (int mt = 0; mt < 4; mt++) {
                    const unsigned* ab = c_s + (mb + mt * 16 + gid) * PXS + h * 16 + k2 + tg;
                    a[mt][0] = ab[0];
                    a[mt][1] = ab[8 * PXS];
                    a[mt][2] = ab[4];
                    a[mt][3] = ab[8 * PXS + 4];
                }
                hprev = h;
            }
            const unsigned* gp = gm_s + (nb + nt * 8 + gid) * 20 + k2 + tg;
            unsigned b0 = gp[0], b1 = gp[4];
#pragma unroll
            for (int mt = 0; mt < 4; mt++) mma_bf16(acc[mt][nt], a[mt], b0, b1);
        }
    }
    __syncthreads();   // everyone done reading cond before t overwrites c_s

    // t = mi * v  -> bf16x2 in place over c_s
#pragma unroll
    for (int mt = 0; mt < 4; mt++)
#pragma unroll
        for (int nt = 0; nt < 6; nt++) {
            int px = mb + mt * 16 + gid, cp = (nb + nt * 8) / 2 + tg;
            float2 v0 = unpbf(__ldg(&g_v[(size_t)(p0 + px) * 96 + cp]));
            float2 v1 = unpbf(__ldg(&g_v[(size_t)(p0 + px + 8) * 96 + cp]));
            c_s[px * PXS + cp]       = packbf(acc[mt][nt][0] * v0.x, acc[mt][nt][1] * v0.y);
            c_s[(px + 8) * PXS + cp] = packbf(acc[mt][nt][2] * v1.x, acc[mt][nt][3] * v1.y);
        }
    __syncthreads();

    // softmax over head-dim (32 ch) per (px, head); in place bf16x2
#pragma unroll
    for (int k = 0; k < 3; k++) {
        int task = tid + k * 256;
        int px = task & 127, h = task >> 7;
        unsigned* row = c_s + px * PXS + h * 16;
        float e[32];
        float m = -1e30f;
#pragma unroll
        for (int j = 0; j < 16; j++) {
            float2 f = unpbf(row[j]);
            e[2 * j] = f.x; e[2 * j + 1] = f.y;
            m = fmaxf(m, fmaxf(f.x, f.y));
        }
        float s = 0.f;
#pragma unroll
        for (int d = 0; d < 32; d++) {
            e[d] = __expf(e[d] - m);
            s += e[d];
        }
        float r = 1.f / s;
#pragma unroll
        for (int j = 0; j < 16; j++) row[j] = packbf(e[2 * j] * r, e[2 * j + 1] * r);
    }

    // proj GEMM + residual (db gemm's internal barrier orders softmax writes)
#pragma unroll
    for (int mt = 0; mt < 4; mt++)
#pragma unroll
        for (int nt = 0; nt < 6; nt++)
#pragma unroll
            for (int r = 0; r < 4; r++) acc[mt][nt][r] = 0.f;
    gemm_db128(c_s, w_s, g_wbf + 4 * MS, acc, tid);
#pragma unroll
    for (int mt = 0; mt < 4; mt++)
#pragma unroll
        for (int nt = 0; nt < 6; nt++) {
            int o = nb + nt * 8 + 2 * tg;
            size_t i00 = (size_t)o * HW + p0 + mb + mt * 16 + gid;
            out[i00]          = acc[mt][nt][0] + __ldg(&x[i00]);
            out[i00 + HW]     = acc[mt][nt][1] + __ldg(&x[i00 + HW]);
            out[i00 + 8]      = acc[mt][nt][2] + __ldg(&x[i00 + 8]);
            out[i00 + HW + 8] = acc[mt][nt][3] + __ldg(&x[i00 + HW + 8]);
        }
}

// ---------------- launch -----------------------------------------------------
extern "C" void kernel_launch(void* const* d_in, const int* in_sizes, int n_in,
                              void* d_out, int out_size) {
    const float* x      = (const float*)d_in[0];
    const float* cond   = (const float*)d_in[1];
    const float* ln_g   = (const float*)d_in[2];
    const float* ln_b   = (const float*)d_in[3];
    const float* pre_w  = (const float*)d_in[4];
    const float* pre_b  = (const float*)d_in[5];
    const float* qkv_w  = (const float*)d_in[6];
    const float* mn_w   = (const float*)d_in[7];
    const float* gating = (const float*)d_in[8];
    const float* proj_w = (const float*)d_in[9];
    float* out = (float*)d_out;

    const int SM12 = (6912 + 6400 + 6912 + 2 * WBUF + 512) * 4;   // 108544 B
    const int SM4  = (12800 + 2 * WBUF + 192 * 20) * 4;           // 92160 B
    cudaFuncSetAttribute(k12, cudaFuncAttributeMaxDynamicSharedMemorySize, SM12);
    cudaFuncSetAttribute(k4,  cudaFuncAttributeMaxDynamicSharedMemorySize, SM4);

    prep_kernel<<<(5 * MS + 255) / 256, 256>>>(pre_w, qkv_w, proj_w);
    k12<<<HW / TPA, 256, SM12>>>(x, ln_g, ln_b, pre_b);
    gmk_kernel<<<12, 256>>>(mn_w, gating);
    k4<<<HW / TPB, 256, SM4>>>(cond, x, out);
}